// round 5
// baseline (speedup 1.0000x reference)
#include <cuda_runtime.h>

// noiseRNN: h_t = tanh(W_ih x_t + b_ih + W_hh h_{t-1} + b_hh); carry h_t + 0.1*noise_t
// T=2048, B=256, I=64, H=128. Batch rows independent -> 128 blocks x 2 batches,
// persistent over all T steps. W held in registers (4j x 24k tile/thread),
// z = [h; x_t] (K=192) broadcast from SMEM, packed f32x2 FMAs, SMEM partial reduce.

#define T_STEPS 2048
#define BATCH   256
#define IN_DIM  64
#define HID     128
#define KDIM    192           // HID + IN_DIM
#define STD_F   0.1f

#define NWARPS  8
#define KSLICE  24            // KDIM / NWARPS
#define THREADS 256

__device__ __forceinline__ unsigned long long fma2(unsigned long long a,
                                                   unsigned long long b,
                                                   unsigned long long c) {
    unsigned long long d;
    asm("fma.rn.f32x2 %0, %1, %2, %3;" : "=l"(d) : "l"(a), "l"(b), "l"(c));
    return d;
}
__device__ __forceinline__ unsigned long long packf2(float lo, float hi) {
    return (unsigned long long)__float_as_uint(lo) |
           ((unsigned long long)__float_as_uint(hi) << 32);
}
__device__ __forceinline__ float lo_f(unsigned long long v) {
    return __uint_as_float((unsigned)v);
}
__device__ __forceinline__ float hi_f(unsigned long long v) {
    return __uint_as_float((unsigned)(v >> 32));
}

__global__ void __launch_bounds__(THREADS, 1) noise_rnn_kernel(
    const float* __restrict__ x,         // [T,B,I]
    const float* __restrict__ w_ih,      // [H,I]
    const float* __restrict__ w_hh,      // [H,H]
    const float* __restrict__ b_ih,      // [H]
    const float* __restrict__ b_hh,      // [H]
    const float* __restrict__ noise,     // [T,B,H]
    const float* __restrict__ hidden_in, // [1,B,H]
    float* __restrict__ out,             // [T,B,H] (+ [1,B,H] h_last)
    int out_size)
{
    // z vectors for the two batches this block owns (batch-major for k-pair f32x2)
    __shared__ __align__(16) float zA[KDIM];
    __shared__ __align__(16) float zB[KDIM];
    // partials: [warp][j*2 + b]  (8 x 256 floats = 8 KB)
    __shared__ __align__(16) float psh[NWARPS * 256];
    __shared__ float bias[HID];

    const int tid   = threadIdx.x;
    const int lane  = tid & 31;
    const int warp  = tid >> 5;
    const int b0    = blockIdx.x * 2;
    const int jbase = lane * 4;        // this thread's 4 output rows
    const int ks    = warp * KSLICE;   // this thread's k-slice start

    // reduction role: thread tid handles output (j = tid>>1, b = tid&1)
    const int rj = tid >> 1;
    const int rb = tid & 1;
    const int gb = b0 + rb;            // global batch index for reduction role

    // --- Load W_cat tile into registers, packed per (k, k+1) pair ---
    // W_cat[j][k] = k < HID ? w_hh[j][k] : w_ih[j][k-HID]
    unsigned long long wpk[4][12];
#pragma unroll
    for (int p = 0; p < 12; ++p) {
        const int k0 = ks + 2 * p;
        const int k1 = k0 + 1;
#pragma unroll
        for (int jj = 0; jj < 4; ++jj) {
            const int j = jbase + jj;
            const float lo = (k0 < HID) ? w_hh[j * HID + k0]
                                        : w_ih[j * IN_DIM + (k0 - HID)];
            const float hi = (k1 < HID) ? w_hh[j * HID + k1]
                                        : w_ih[j * IN_DIM + (k1 - HID)];
            wpk[jj][p] = packf2(lo, hi);
        }
    }

    // --- Init bias and z for t = 0 ---
    if (tid < HID) bias[tid] = b_ih[tid] + b_hh[tid];
    {
        float* zp = rb ? zB : zA;
        zp[rj] = hidden_in[gb * HID + rj];           // h0
        if (tid < 2 * IN_DIM)
            zp[HID + rj] = x[gb * IN_DIM + rj];      // x[0]  (rj = tid>>1 < 64)
    }
    __syncthreads();

    const int noise_base = gb * HID + rj;
    const int x_base     = gb * IN_DIM + rj;
    const int out_base   = gb * HID + rj;

    for (int t = 0; t < T_STEPS; ++t) {
        // Prefetch this step's noise and next step's x (latency hides under matvec)
        const float nz = noise[t * (BATCH * HID) + noise_base];
        float xn = 0.0f;
        const bool ldx = (tid < 2 * IN_DIM) && (t + 1 < T_STEPS);
        if (ldx) xn = x[(t + 1) * (BATCH * IN_DIM) + x_base];

        // --- matvec partials over this thread's k-slice, both batches ---
        unsigned long long accA[4] = {0ull, 0ull, 0ull, 0ull};
        unsigned long long accB[4] = {0ull, 0ull, 0ull, 0ull};
        const ulonglong2* zAp = reinterpret_cast<const ulonglong2*>(zA + ks);
        const ulonglong2* zBp = reinterpret_cast<const ulonglong2*>(zB + ks);
#pragma unroll
        for (int q = 0; q < 6; ++q) {
            const ulonglong2 va = zAp[q];   // z[k..k+3] batch A (broadcast LDS.128)
            const ulonglong2 vb = zBp[q];   // z[k..k+3] batch B
#pragma unroll
            for (int jj = 0; jj < 4; ++jj) {
                accA[jj] = fma2(wpk[jj][2 * q],     va.x, accA[jj]);
                accA[jj] = fma2(wpk[jj][2 * q + 1], va.y, accA[jj]);
                accB[jj] = fma2(wpk[jj][2 * q],     vb.x, accB[jj]);
                accB[jj] = fma2(wpk[jj][2 * q + 1], vb.y, accB[jj]);
            }
        }

        // --- store partials (horizontal add of the f32x2 halves) ---
        {
            float4 p0, p1;
            p0.x = lo_f(accA[0]) + hi_f(accA[0]);
            p0.y = lo_f(accB[0]) + hi_f(accB[0]);
            p0.z = lo_f(accA[1]) + hi_f(accA[1]);
            p0.w = lo_f(accB[1]) + hi_f(accB[1]);
            p1.x = lo_f(accA[2]) + hi_f(accA[2]);
            p1.y = lo_f(accB[2]) + hi_f(accB[2]);
            p1.z = lo_f(accA[3]) + hi_f(accA[3]);
            p1.w = lo_f(accB[3]) + hi_f(accB[3]);
            float4* pp = reinterpret_cast<float4*>(psh + warp * 256 + jbase * 2);
            pp[0] = p0;
            pp[1] = p1;
        }
        __syncthreads();

        // --- reduce: thread tid owns output (rj, rb); psh index j*2+b == tid ---
        float s = bias[rj];
#pragma unroll
        for (int w = 0; w < NWARPS; ++w) s += psh[w * 256 + tid];

        const float hn = tanhf(s);
        out[t * (BATCH * HID) + out_base] = hn;

        const float zn = hn + STD_F * nz;       // noisy carried state
        float* zp = rb ? zB : zA;
        zp[rj] = zn;
        if (ldx) zp[HID + rj] = xn;             // stage next x into z

        if (t == T_STEPS - 1 && out_size > T_STEPS * BATCH * HID)
            out[T_STEPS * (BATCH * HID) + out_base] = zn;   // h_last

        __syncthreads();
    }
}

extern "C" void kernel_launch(void* const* d_in, const int* in_sizes, int n_in,
                              void* d_out, int out_size) {
    const float* x         = (const float*)d_in[0];
    const float* w_ih      = (const float*)d_in[1];
    const float* w_hh      = (const float*)d_in[2];
    const float* b_ih      = (const float*)d_in[3];
    const float* b_hh      = (const float*)d_in[4];
    const float* noise     = (const float*)d_in[5];
    const float* hidden_in = (const float*)d_in[6];
    float* out = (float*)d_out;

    noise_rnn_kernel<<<BATCH / 2, THREADS>>>(x, w_ih, w_hh, b_ih, b_hh,
                                             noise, hidden_in, out, out_size);
}